// round 16
// baseline (speedup 1.0000x reference)
#include <cuda_runtime.h>
#include <cuda_bf16.h>

#define QN      400
#define PN      200000
#define NLAB    100
#define KS      4
#define THREADS 128
#define CHUNK   (PN / KS)                 // 50000 = 16 * 3125
#define W       16
#define SSTEP   (THREADS * W)             // 2048
#define NSTAGE  4
#define NCOPY   32
#define BINB    (NLAB * NCOPY * 4)        // 12800 B
#define STG_P   BINB                      // pred stages: NSTAGE * 8192 B
#define STG_L   (BINB + NSTAGE * 8192)    // label stages: NSTAGE * 2048 B
#define SMEMSZ  (BINB + NSTAGE * 8192 + NSTAGE * 2048)   // 53760 B -> 4 CTAs/SM
#define CVT_BLOCKS ((PN / 4 + 255) / 256) // 196

// ---------------- device scratch (no allocation allowed) ----------------
__device__ unsigned char g_lab8[PN];
__device__ int   g_blockhist[CVT_BLOCKS * NLAB];
__device__ float g_partial[KS * QN * NLAB * 2];   // [r][q][lab][{d,s}]
__device__ float g_totals[KS * QN * 2];           // [r][q][{f0tot, ptot}]

// ---------------- kernel 0: narrow labels to u8 + per-block histogram ----------------
__global__ void convert_labels(const int* __restrict__ labels) {
    __shared__ int hist[NLAB];
    const int tid = threadIdx.x;
    for (int i = tid; i < NLAB; i += 256) hist[i] = 0;
    __syncthreads();

    int i = blockIdx.x * blockDim.x + tid;
    int base = i * 4;
    if (base < PN) {
        int4 l = *(const int4*)(labels + base);
        uchar4 u;
        u.x = (unsigned char)l.x; u.y = (unsigned char)l.y;
        u.z = (unsigned char)l.z; u.w = (unsigned char)l.w;
        *(uchar4*)(g_lab8 + base) = u;
        atomicAdd(&hist[l.x], 1); atomicAdd(&hist[l.y], 1);
        atomicAdd(&hist[l.z], 1); atomicAdd(&hist[l.w], 1);
    }
    __syncthreads();
    for (int j = tid; j < NLAB; j += 256)
        g_blockhist[blockIdx.x * NLAB + j] = hist[j];
}

// ---------------- helpers ----------------
static __device__ __forceinline__ unsigned saddr(const void* p) {
    unsigned a;
    asm("{.reg .u64 t; cvta.to.shared.u64 t, %1; cvt.u32.u64 %0, t;}" : "=r"(a) : "l"(p));
    return a;
}

// ---- branch-free transform: 3 MUFU, no selects. Safe for |x| < 80. ----
static __device__ __forceinline__ void xform(float x, float& d, float& p, float& f0) {
    float t, lg;
    asm("ex2.approx.f32 %0, %1;" : "=f"(t) : "f"(x * -1.4426950408889634f)); // e^-x
    float opt = 1.0f + t;
    asm("rcp.approx.f32 %0, %1;" : "=f"(p)  : "f"(opt));   // p = sigmoid(x)
    asm("lg2.approx.f32 %0, %1;" : "=f"(lg) : "f"(opt));
    float logp = lg * -0.69314718055994531f;               // log sigmoid(x)
    float l1mp = logp - x;                                 // log sigmoid(-x)
    float omp  = t * p;                                    // 1 - p, exact identity
    f0 = (p * p) * (l1mp * -0.75f);
    float f1 = (omp * omp) * (logp * -0.25f);
    d = f1 - f0;
}

// ---- fused per-element: transform + fire-and-forget bf16x2 shared reduction ----
static __device__ __forceinline__ void elem(float x, unsigned lw, int i,
                                            unsigned binlane, float& accf0) {
    int l = (int)((lw >> (8 * i)) & 0xffu);
    unsigned addr = binlane + (unsigned)l * (NCOPY * 4);   // bins[l][lane%32]
    float d, p, f0;
    xform(x, d, p, f0);
    accf0 += f0;
    __nv_bfloat162 v = __floats2bfloat162_rn(d, p);        // .x=d, .y=p
    asm volatile("red.shared.add.noftz.bf16x2 [%0], %1;"
                 :: "r"(addr), "r"(*(unsigned*)&v) : "memory");
}

// cp.async one 16-element slice (4x16B pred + 16B labels) into stage slot
static __device__ __forceinline__ void stage_issue(const float* __restrict__ row,
                                                   const unsigned char* __restrict__ lab,
                                                   unsigned sbase, int slot, int idx, int tid) {
    if (idx < CHUNK) {
        unsigned pd = sbase + STG_P + slot * 8192 + tid * 16;
        unsigned ld = sbase + STG_L + slot * 2048 + tid * 16;
        const float* g = row + idx;
        #pragma unroll
        for (int i = 0; i < 4; i++)
            asm volatile("cp.async.cg.shared.global [%0], [%1], 16;"
                         :: "r"(pd + i * 2048), "l"(g + i * 4) : "memory");
        asm volatile("cp.async.cg.shared.global [%0], [%1], 16;"
                     :: "r"(ld), "l"(lab + idx) : "memory");
    }
    asm volatile("cp.async.commit_group;" ::: "memory");
}

// ---------------- kernel 1: main segmented reduction (cp.async staged, RED bins) ----------------
__global__ __launch_bounds__(THREADS, 4)
void main_kernel(const float* __restrict__ pred) {
    extern __shared__ char smem[];
    const int tid = threadIdx.x;
    const int q = blockIdx.x;
    const int r = blockIdx.y;

    // zero bins (12800 B)
    uint4* z4 = (uint4*)smem;
    for (int i = tid; i < BINB / 16; i += THREADS)
        z4[i] = make_uint4(0u, 0u, 0u, 0u);
    __syncthreads();

    const unsigned sbase = saddr(smem);
    const unsigned binlane = sbase + (unsigned)(tid & (NCOPY - 1)) * 4u;
    const float* row = pred + (size_t)q * PN + (size_t)r * CHUNK;
    const unsigned char* lab = g_lab8 + (size_t)r * CHUNK;

    // ---- prologue: stages 0..2 in flight ----
    stage_issue(row, lab, sbase, 0, tid * W,             tid);
    stage_issue(row, lab, sbase, 1, tid * W + SSTEP,     tid);
    stage_issue(row, lab, sbase, 2, tid * W + 2 * SSTEP, tid);

    float accf0 = 0.f;
    int idx = tid * W;
    int k = 0;
    while (idx < CHUNK) {
        asm volatile("cp.async.wait_group 2;" ::: "memory");  // stage k arrived (per-thread)

        const int slot = k & (NSTAGE - 1);
        const float4* sp = (const float4*)(smem + STG_P + slot * 8192 + tid * 16);
        float4 A0 = sp[0];
        float4 A1 = sp[128];
        float4 A2 = sp[256];
        float4 A3 = sp[384];
        uint4  LW = *(const uint4*)(smem + STG_L + slot * 2048 + tid * 16);

        elem(A0.x, LW.x, 0, binlane, accf0);
        elem(A0.y, LW.x, 1, binlane, accf0);
        elem(A0.z, LW.x, 2, binlane, accf0);
        elem(A0.w, LW.x, 3, binlane, accf0);
        elem(A1.x, LW.y, 0, binlane, accf0);
        elem(A1.y, LW.y, 1, binlane, accf0);
        elem(A1.z, LW.y, 2, binlane, accf0);
        elem(A1.w, LW.y, 3, binlane, accf0);
        elem(A2.x, LW.z, 0, binlane, accf0);
        elem(A2.y, LW.z, 1, binlane, accf0);
        elem(A2.z, LW.z, 2, binlane, accf0);
        elem(A2.w, LW.z, 3, binlane, accf0);
        elem(A3.x, LW.w, 0, binlane, accf0);
        elem(A3.y, LW.w, 1, binlane, accf0);
        elem(A3.z, LW.w, 2, binlane, accf0);
        elem(A3.w, LW.w, 3, binlane, accf0);

        // refill: stage k+3 into slot (k+3)&3 (reads of slot finished above, same thread)
        stage_issue(row, lab, sbase, (k + 3) & (NSTAGE - 1), idx + 3 * SSTEP, tid);

        idx += SSTEP;
        k++;
    }
    asm volatile("cp.async.wait_group 0;" ::: "memory");
    __syncthreads();   // drain REDs, order bins for cross-warp read

    // reduce 32 copies per label -> deterministic partial buffer (exact f32)
    const __nv_bfloat162* bins = (const __nv_bfloat162*)smem;
    float ss = 0.f;
    if (tid < NLAB) {
        float ds = 0.f;
        #pragma unroll 8
        for (int i = 0; i < NCOPY; i++) {
            float2 v = __bfloat1622float2(bins[tid * NCOPY + ((i + tid) & (NCOPY - 1))]);
            ds += v.x; ss += v.y;
        }
        int o = ((r * QN + q) * NLAB + tid) * 2;
        g_partial[o]     = ds;
        g_partial[o + 1] = ss;
    }
    __syncthreads();

    // total p = sum of ss over all labels (every point has exactly one label)
    float* sred = (float*)smem;
    sred[tid] = ss;
    __syncthreads();
    #pragma unroll
    for (int s = THREADS / 2; s >= 32; s >>= 1) {
        if (tid < s) sred[tid] += sred[tid + s];
        __syncthreads();
    }
    if (tid < 32) {
        float v = sred[tid];
        #pragma unroll
        for (int off = 16; off; off >>= 1) v += __shfl_down_sync(0xffffffffu, v, off);
        if (tid == 0) g_totals[(r * QN + q) * 2 + 1] = v;
    }

    // row total f0 (exact f32 path)
    #pragma unroll
    for (int off = 16; off; off >>= 1)
        accf0 += __shfl_down_sync(0xffffffffu, accf0, off);
    __shared__ float ws[4];
    if ((tid & 31) == 0) ws[tid >> 5] = accf0;
    __syncthreads();
    if (tid == 0)
        g_totals[(r * QN + q) * 2 + 0] = ws[0] + ws[1] + ws[2] + ws[3];
}

// ---------------- kernel 2: counts + cost assembly ----------------
__global__ void finalize(float* __restrict__ out) {
    const int j = blockIdx.x;           // label 0..99
    const int tid = threadIdx.x;        // 256 threads

    int c = 0;
    for (int b = tid; b < CVT_BLOCKS; b += 256)
        c += g_blockhist[b * NLAB + j];
    #pragma unroll
    for (int off = 16; off; off >>= 1) c += __shfl_down_sync(0xffffffffu, c, off);
    __shared__ int cs[8];
    if ((tid & 31) == 0) cs[tid >> 5] = c;
    __syncthreads();
    int cnt = 0;
    #pragma unroll
    for (int w = 0; w < 8; w++) cnt += cs[w];
    float fc = (float)cnt;

    for (int q = tid; q < QN; q += 256) {
        float dsum = 0.f, ssum = 0.f, f0t = 0.f, pt = 0.f;
        #pragma unroll
        for (int r = 0; r < KS; r++) {
            int bi = ((r * QN + q) * NLAB + j) * 2;
            dsum += g_partial[bi];
            ssum += g_partial[bi + 1];
            f0t  += g_totals[(r * QN + q) * 2 + 0];
            pt   += g_totals[(r * QN + q) * 2 + 1];
        }
        float cmask = (dsum + f0t) * (1.0f / (float)PN);
        float dice  = 1.0f - (2.0f * ssum + 1.0f) / (pt + fc + 1.0f);
        out[q * NLAB + j] = cmask + dice;
    }
}

// ---------------- launch ----------------
extern "C" void kernel_launch(void* const* d_in, const int* in_sizes, int n_in,
                              void* d_out, int out_size) {
    const float* pred  = (const float*)d_in[0];
    const int* labels  = (const int*)d_in[1];
    float* out = (float*)d_out;

    cudaFuncSetAttribute(main_kernel,
                         cudaFuncAttributeMaxDynamicSharedMemorySize, SMEMSZ);

    convert_labels<<<CVT_BLOCKS, 256>>>(labels);
    dim3 grid(QN, KS);
    main_kernel<<<grid, THREADS, SMEMSZ>>>(pred);
    finalize<<<NLAB, 256>>>(out);
}